// round 9
// baseline (speedup 1.0000x reference)
#include <cuda_runtime.h>

#define N_NODES 50000
#define E_MAX   800000
#define D_HID   128
#define D_OUT   64

// ---------------- device scratch (16B-aligned; no allocations allowed) ----------------
__device__ __align__(16) float g_hs1 [N_NODES * D_HID];  // (x@W1)  * dinv[row]
__device__ __align__(16) float g_x2  [N_NODES * D_HID];  // layer-1 output (post relu)
__device__ __align__(16) float g_hs2 [N_NODES * D_OUT];  // (x2@W2) * dinv[row]
__device__ float g_dinv[N_NODES];                        // 1/sqrt(deg+1)
__device__ int   g_cur [N_NODES];                        // counts, then fill cursor
__device__ int   g_off [N_NODES + 1];                    // CSR offsets (by dst)
__device__ int   g_bsum[64];                             // chunk sums for scan
__device__ int   g_is64;                                 // edge dtype flag
__device__ int   g_src [E_MAX];                          // normalized src indices
__device__ int   g_dst [E_MAX];                          // normalized dst indices
__device__ int   g_esrc[E_MAX];                          // CSR: src per edge slot

static inline int cdiv(int a, int b) { return (a + b - 1) / b; }

// ---------------- edge dtype detection + normalization ----------------
// If edge data is int64 (values < 50000), every odd 32-bit word is a zero
// high-half. If int32, odd words are random node ids; P(1024 all zero) ~ 0.
__global__ void detect_kernel(const unsigned int* __restrict__ w) {
    __shared__ int anynz;
    if (threadIdx.x == 0) anynz = 0;
    __syncthreads();
    if (w[2 * threadIdx.x + 1] != 0u) anynz = 1;  // benign race (same value)
    __syncthreads();
    if (threadIdx.x == 0) g_is64 = (anynz == 0) ? 1 : 0;
}

__global__ void convert_kernel(const void* __restrict__ ei, int E) {
    int e = blockIdx.x * blockDim.x + threadIdx.x;
    if (e >= E) return;
    if (g_is64) {
        const long long* p = (const long long*)ei;
        g_src[e] = (int)p[e];
        g_dst[e] = (int)p[E + e];
    } else {
        const int* p = (const int*)ei;
        g_src[e] = p[e];
        g_dst[e] = p[E + e];
    }
}

// ---------------- CSR build (counting sort by dst) ----------------

__global__ void zero_cnt_kernel() {
    int i = blockIdx.x * blockDim.x + threadIdx.x;
    if (i < N_NODES) g_cur[i] = 0;
}

__global__ void count_kernel(int E) {
    int e = blockIdx.x * blockDim.x + threadIdx.x;
    if (e < E) atomicAdd(&g_cur[g_dst[e]], 1);
}

// k1: per-1024-chunk exclusive scan of g_cur into g_off; chunk sum -> g_bsum
__global__ void scan1_kernel(int n) {
    int i = blockIdx.x * 1024 + threadIdx.x;
    int lane = threadIdx.x & 31;
    int wid  = threadIdx.x >> 5;
    int v = (i < n) ? g_cur[i] : 0;

    int incl = v;
#pragma unroll
    for (int d = 1; d < 32; d <<= 1) {
        int t = __shfl_up_sync(0xffffffffu, incl, d);
        if (lane >= d) incl += t;
    }
    __shared__ int ws[32];
    if (lane == 31) ws[wid] = incl;
    __syncthreads();
    if (wid == 0) {
        int wincl = ws[lane];
#pragma unroll
        for (int d = 1; d < 32; d <<= 1) {
            int t = __shfl_up_sync(0xffffffffu, wincl, d);
            if (lane >= d) wincl += t;
        }
        ws[lane] = wincl;
    }
    __syncthreads();
    int warpoff = (wid > 0) ? ws[wid - 1] : 0;
    if (i < n) g_off[i] = incl - v + warpoff;              // exclusive within chunk
    if (threadIdx.x == 1023) g_bsum[blockIdx.x] = ws[31];  // chunk total
}

// k2: exclusive scan of <=64 chunk sums (single block of 64 threads)
__global__ void scan2_kernel(int nblk) {
    __shared__ int buf[64];
    int t = threadIdx.x;
    int v = (t < nblk) ? g_bsum[t] : 0;
    buf[t] = v;
    __syncthreads();
#pragma unroll
    for (int d = 1; d < 64; d <<= 1) {
        int a = (t >= d) ? buf[t - d] : 0;
        __syncthreads();
        buf[t] += a;
        __syncthreads();
    }
    if (t < nblk) g_bsum[t] = buf[t] - v;  // exclusive
}

// k3: add chunk base; set sentinel; cursor = offsets
__global__ void scan3_kernel(int n, int E) {
    int i = blockIdx.x * blockDim.x + threadIdx.x;
    if (i < n) {
        int o = g_off[i] + g_bsum[i >> 10];
        g_off[i] = o;
        g_cur[i] = o;
    }
    if (i == 0) g_off[n] = E;
}

__global__ void fill_kernel(int E) {
    int e = blockIdx.x * blockDim.x + threadIdx.x;
    if (e < E) {
        int d = g_dst[e];
        int p = atomicAdd(&g_cur[d], 1);
        g_esrc[p] = g_src[e];
    }
}

__global__ void dinv_kernel() {
    int i = blockIdx.x * blockDim.x + threadIdx.x;
    if (i < N_NODES) {
        float deg = (float)(g_off[i + 1] - g_off[i]);
        g_dinv[i] = rsqrtf(deg + 1.0f);  // +1 = self loop
    }
}

// ---------------- GEMM + row scale:  out[m] = dinv[m] * (x[m] @ W) ----------------
// K == 128.  blockDim = (N/4, ROWS); each thread: 1 row, 4 contiguous cols.
// N_NODES % ROWS == 0, so no tail guards.
template <int N, int ROWS>
__device__ __forceinline__ void gemm_scale_body(const float* __restrict__ x,
                                                const float* __restrict__ W,
                                                float* __restrict__ out) {
    constexpr int K = 128;
    __shared__ __align__(16) float xs[ROWS][K];
    const int row0 = blockIdx.x * ROWS;
    const int tx = threadIdx.x, ty = threadIdx.y;
    const int tid = ty * (N / 4) + tx;
    const int nthr = (N / 4) * ROWS;

    const float4* x4 = reinterpret_cast<const float4*>(x);
    for (int i = tid; i < ROWS * (K / 4); i += nthr) {
        int r = i / (K / 4), c = i % (K / 4);
        reinterpret_cast<float4*>(&xs[r][0])[c] = x4[(size_t)(row0 + r) * (K / 4) + c];
    }
    __syncthreads();

    const int row = row0 + ty;
    const float4* W4 = reinterpret_cast<const float4*>(W);
    float4 acc = make_float4(0.f, 0.f, 0.f, 0.f);
#pragma unroll 8
    for (int k = 0; k < K; k++) {
        float4 w = W4[k * (N / 4) + tx];
        float xv = xs[ty][k];
        acc.x += xv * w.x; acc.y += xv * w.y;
        acc.z += xv * w.z; acc.w += xv * w.w;
    }
    float d = g_dinv[row];
    acc.x *= d; acc.y *= d; acc.z *= d; acc.w *= d;
    reinterpret_cast<float4*>(out)[(size_t)row * (N / 4) + tx] = acc;
}

__global__ void gemm1_kernel(const float* __restrict__ x, const float* __restrict__ W) {
    gemm_scale_body<128, 8>(x, W, g_hs1);
}
__global__ void gemm2_kernel(const float* __restrict__ W) {
    gemm_scale_body<64, 16>(g_x2, W, g_hs2);
}

// ---------------- gather + finalize (layer 1, N=128, relu) ----------------
// One warp per node; each lane owns one float4 column chunk (32 * 4 = 128).
__global__ void gather1_kernel(const float* __restrict__ b) {
    int warp = (blockIdx.x * blockDim.x + threadIdx.x) >> 5;
    int lane = threadIdx.x & 31;
    if (warp >= N_NODES) return;
    const float4* hs4 = reinterpret_cast<const float4*>(g_hs1);

    float4 acc = hs4[(size_t)warp * 32 + lane];  // self-loop term
    int e = g_off[warp], end = g_off[warp + 1];
    for (; e + 4 <= end; e += 4) {
        int s0 = g_esrc[e], s1 = g_esrc[e + 1], s2 = g_esrc[e + 2], s3 = g_esrc[e + 3];
        float4 v0 = hs4[(size_t)s0 * 32 + lane];
        float4 v1 = hs4[(size_t)s1 * 32 + lane];
        float4 v2 = hs4[(size_t)s2 * 32 + lane];
        float4 v3 = hs4[(size_t)s3 * 32 + lane];
        acc.x += v0.x + v1.x + v2.x + v3.x;
        acc.y += v0.y + v1.y + v2.y + v3.y;
        acc.z += v0.z + v1.z + v2.z + v3.z;
        acc.w += v0.w + v1.w + v2.w + v3.w;
    }
    for (; e < end; e++) {
        int s = g_esrc[e];
        float4 v = hs4[(size_t)s * 32 + lane];
        acc.x += v.x; acc.y += v.y; acc.z += v.z; acc.w += v.w;
    }
    float d = g_dinv[warp];
    float4 bv = reinterpret_cast<const float4*>(b)[lane];
    float4 o;
    o.x = fmaxf(fmaf(d, acc.x, bv.x), 0.f);
    o.y = fmaxf(fmaf(d, acc.y, bv.y), 0.f);
    o.z = fmaxf(fmaf(d, acc.z, bv.z), 0.f);
    o.w = fmaxf(fmaf(d, acc.w, bv.w), 0.f);
    reinterpret_cast<float4*>(g_x2)[(size_t)warp * 32 + lane] = o;
}

// ---------------- gather + finalize (layer 2, N=64, no relu) ----------------
// 16 lanes per node (16 * 4 = 64 floats).
__global__ void gather2_kernel(const float* __restrict__ b,
                               float* __restrict__ out) {
    int t = blockIdx.x * blockDim.x + threadIdx.x;
    int node = t >> 4;
    int l = t & 15;
    if (node >= N_NODES) return;
    const float4* hs4 = reinterpret_cast<const float4*>(g_hs2);

    float4 acc = hs4[(size_t)node * 16 + l];  // self-loop term
    int e = g_off[node], end = g_off[node + 1];
    for (; e + 4 <= end; e += 4) {
        int s0 = g_esrc[e], s1 = g_esrc[e + 1], s2 = g_esrc[e + 2], s3 = g_esrc[e + 3];
        float4 v0 = hs4[(size_t)s0 * 16 + l];
        float4 v1 = hs4[(size_t)s1 * 16 + l];
        float4 v2 = hs4[(size_t)s2 * 16 + l];
        float4 v3 = hs4[(size_t)s3 * 16 + l];
        acc.x += v0.x + v1.x + v2.x + v3.x;
        acc.y += v0.y + v1.y + v2.y + v3.y;
        acc.z += v0.z + v1.z + v2.z + v3.z;
        acc.w += v0.w + v1.w + v2.w + v3.w;
    }
    for (; e < end; e++) {
        int s = g_esrc[e];
        float4 v = hs4[(size_t)s * 16 + l];
        acc.x += v.x; acc.y += v.y; acc.z += v.z; acc.w += v.w;
    }
    float d = g_dinv[node];
    float4 bv = reinterpret_cast<const float4*>(b)[l];
    float4 o;
    o.x = fmaf(d, acc.x, bv.x);
    o.y = fmaf(d, acc.y, bv.y);
    o.z = fmaf(d, acc.z, bv.z);
    o.w = fmaf(d, acc.w, bv.w);
    reinterpret_cast<float4*>(out)[(size_t)node * 16 + l] = o;
}

// ---------------- launch (no runtime API calls, no host symbol refs) ----------------

extern "C" void kernel_launch(void* const* d_in, const int* in_sizes, int n_in,
                              void* d_out, int out_size) {
    const float* x   = (const float*)d_in[0];
    const void*  ei  = d_in[1];                 // int32 OR int64 [2, E] — detected on device
    const float* W1  = (const float*)d_in[2];
    const float* b1  = (const float*)d_in[3];
    const float* W2  = (const float*)d_in[4];
    const float* b2  = (const float*)d_in[5];
    float*       out = (float*)d_out;

    const int E = in_sizes[1] / 2;
    const int n = N_NODES;

    // ---- edge dtype detect + normalize to int32 ----
    detect_kernel<<<1, 1024>>>((const unsigned int*)ei);
    convert_kernel<<<cdiv(E, 256), 256>>>(ei, E);

    // ---- CSR build by dst ----
    zero_cnt_kernel<<<cdiv(n, 256), 256>>>();
    count_kernel<<<cdiv(E, 256), 256>>>(E);
    scan1_kernel<<<cdiv(n, 1024), 1024>>>(n);
    scan2_kernel<<<1, 64>>>(cdiv(n, 1024));
    scan3_kernel<<<cdiv(n, 256), 256>>>(n, E);
    fill_kernel<<<cdiv(E, 256), 256>>>(E);
    dinv_kernel<<<cdiv(n, 256), 256>>>();

    // ---- layer 1 ----
    {
        dim3 blk(32, 8);                     // N/4 = 32 lanes x 8 rows
        gemm1_kernel<<<n / 8, blk>>>(x, W1);
    }
    gather1_kernel<<<cdiv(n * 32, 256), 256>>>(b1);

    // ---- layer 2 ----
    {
        dim3 blk(16, 16);                    // N/4 = 16 lanes x 16 rows
        gemm2_kernel<<<n / 16, blk>>>(W2);
    }
    gather2_kernel<<<cdiv(n * 16, 256), 256>>>(b2, out);
}

// round 10
// speedup vs baseline: 1.2084x; 1.2084x over previous
#include <cuda_runtime.h>

#define N_NODES 50000
#define E_MAX   800000
#define D_HID   128
#define D_OUT   64

// ---------------- device scratch (16B-aligned; no allocations allowed) ----------------
__device__ __align__(16) float g_hs1 [N_NODES * D_HID];  // (x@W1)  * dinv[row]
__device__ __align__(16) float g_x2  [N_NODES * D_HID];  // layer-1 output (post relu)
__device__ __align__(16) float g_hs2 [N_NODES * D_OUT];  // (x2@W2) * dinv[row]
__device__ float g_dinv[N_NODES];                        // 1/sqrt(deg+1)
__device__ int   g_cur [N_NODES];                        // counts, then fill cursor
__device__ int   g_off [N_NODES + 1];                    // CSR offsets (by dst)
__device__ int   g_bsum[64];                             // chunk sums for scan
__device__ int   g_is64;                                 // edge dtype flag
__device__ int   g_src [E_MAX];                          // normalized src indices
__device__ int   g_dst [E_MAX];                          // normalized dst indices
__device__ int   g_esrc[E_MAX];                          // CSR: src per edge slot

static inline int cdiv(int a, int b) { return (a + b - 1) / b; }

// ---------------- init: zero counts; block 0 also detects edge dtype ----------------
// If edges are int64 (values < 50000) every odd 32-bit word is a zero high half.
// If int32, odd words are random node ids; P(256 all zero) ~ 0.
__global__ void init_kernel(const unsigned int* __restrict__ w) {
    int i = blockIdx.x * blockDim.x + threadIdx.x;
    if (i < N_NODES) g_cur[i] = 0;
    if (blockIdx.x == 0) {
        __shared__ int anynz;
        if (threadIdx.x == 0) anynz = 0;
        __syncthreads();
        if (w[2 * threadIdx.x + 1] != 0u) anynz = 1;  // benign same-value race
        __syncthreads();
        if (threadIdx.x == 0) g_is64 = (anynz == 0) ? 1 : 0;
    }
}

// ---------------- convert + degree count in one pass ----------------
__global__ void convert_count_kernel(const void* __restrict__ ei, int E) {
    int e = blockIdx.x * blockDim.x + threadIdx.x;
    if (e >= E) return;
    int s, d;
    if (g_is64) {
        const long long* p = (const long long*)ei;
        s = (int)p[e];
        d = (int)p[E + e];
    } else {
        const int* p = (const int*)ei;
        s = p[e];
        d = p[E + e];
    }
    g_src[e] = s;
    g_dst[e] = d;
    atomicAdd(&g_cur[d], 1);
}

// ---------------- CSR scan ----------------

// k1: per-1024-chunk exclusive scan of g_cur into g_off; chunk sum -> g_bsum
__global__ void scan1_kernel(int n) {
    int i = blockIdx.x * 1024 + threadIdx.x;
    int lane = threadIdx.x & 31;
    int wid  = threadIdx.x >> 5;
    int v = (i < n) ? g_cur[i] : 0;

    int incl = v;
#pragma unroll
    for (int d = 1; d < 32; d <<= 1) {
        int t = __shfl_up_sync(0xffffffffu, incl, d);
        if (lane >= d) incl += t;
    }
    __shared__ int ws[32];
    if (lane == 31) ws[wid] = incl;
    __syncthreads();
    if (wid == 0) {
        int wincl = ws[lane];
#pragma unroll
        for (int d = 1; d < 32; d <<= 1) {
            int t = __shfl_up_sync(0xffffffffu, wincl, d);
            if (lane >= d) wincl += t;
        }
        ws[lane] = wincl;
    }
    __syncthreads();
    int warpoff = (wid > 0) ? ws[wid - 1] : 0;
    if (i < n) g_off[i] = incl - v + warpoff;              // exclusive within chunk
    if (threadIdx.x == 1023) g_bsum[blockIdx.x] = ws[31];  // chunk total
}

// k2: exclusive scan of <=64 chunk sums
__global__ void scan2_kernel(int nblk) {
    __shared__ int buf[64];
    int t = threadIdx.x;
    int v = (t < nblk) ? g_bsum[t] : 0;
    buf[t] = v;
    __syncthreads();
#pragma unroll
    for (int d = 1; d < 64; d <<= 1) {
        int a = (t >= d) ? buf[t - d] : 0;
        __syncthreads();
        buf[t] += a;
        __syncthreads();
    }
    if (t < nblk) g_bsum[t] = buf[t] - v;  // exclusive
}

// k3: add chunk base; cursor = offsets; dinv from counts (still in g_cur); sentinel
__global__ void scan3_kernel(int n, int E) {
    int i = blockIdx.x * blockDim.x + threadIdx.x;
    if (i < n) {
        int c = g_cur[i];                      // degree (count), pre-overwrite
        int o = g_off[i] + g_bsum[i >> 10];
        g_off[i] = o;
        g_cur[i] = o;
        g_dinv[i] = rsqrtf((float)c + 1.0f);   // +1 = self loop
    }
    if (i == 0) g_off[n] = E;
}

__global__ void fill_kernel(int E) {
    int e = blockIdx.x * blockDim.x + threadIdx.x;
    if (e < E) {
        int d = g_dst[e];
        int p = atomicAdd(&g_cur[d], 1);
        g_esrc[p] = g_src[e];
    }
}

// ---------------- GEMM1:  g_hs1[m] = dinv[m] * (x[m] @ W1),  N=128, K=128 ----------------
// BM=64 rows/CTA, 256 threads, per-thread 4x8 register tile. x tile in smem
// (broadcast LDS); W read through L1 (hot, 64KB).
__global__ __launch_bounds__(256) void gemm1_kernel(const float* __restrict__ x,
                                                    const float* __restrict__ W,
                                                    int M) {
    __shared__ __align__(16) float xs[64][128];
    const int row0 = blockIdx.x * 64;
    const int tid = threadIdx.x;

    // load x tile: 64*128 floats = 2048 float4 over 256 threads, coalesced
    const float4* x4 = reinterpret_cast<const float4*>(x);
    float4* xs4 = reinterpret_cast<float4*>(&xs[0][0]);
#pragma unroll
    for (int i = 0; i < 8; i++) {
        int idx = i * 256 + tid;                 // float4 index in tile
        int r = row0 + (idx >> 5);
        if (r >= M) r = M - 1;                   // clamp (tail tile); stores guarded
        xs4[idx] = x4[(size_t)r * 32 + (idx & 31)];
    }
    __syncthreads();

    const int cg = tid & 15;      // col group: 8 cols
    const int rg = tid >> 4;      // row group: 4 rows
    const int r0 = rg * 4;
    float acc[4][8] = {};
    const float4* W4 = reinterpret_cast<const float4*>(W);  // row = 32 float4
#pragma unroll 4
    for (int k = 0; k < 128; k++) {
        float4 wa = W4[k * 32 + cg * 2];
        float4 wb = W4[k * 32 + cg * 2 + 1];
#pragma unroll
        for (int i = 0; i < 4; i++) {
            float xv = xs[r0 + i][k];
            acc[i][0] += xv * wa.x; acc[i][1] += xv * wa.y;
            acc[i][2] += xv * wa.z; acc[i][3] += xv * wa.w;
            acc[i][4] += xv * wb.x; acc[i][5] += xv * wb.y;
            acc[i][6] += xv * wb.z; acc[i][7] += xv * wb.w;
        }
    }
    float4* out4 = reinterpret_cast<float4*>(g_hs1);
#pragma unroll
    for (int i = 0; i < 4; i++) {
        int row = row0 + r0 + i;
        if (row >= M) break;
        float d = g_dinv[row];
        float4 o0, o1;
        o0.x = acc[i][0] * d; o0.y = acc[i][1] * d;
        o0.z = acc[i][2] * d; o0.w = acc[i][3] * d;
        o1.x = acc[i][4] * d; o1.y = acc[i][5] * d;
        o1.z = acc[i][6] * d; o1.w = acc[i][7] * d;
        out4[(size_t)row * 32 + cg * 2]     = o0;
        out4[(size_t)row * 32 + cg * 2 + 1] = o1;
    }
}

// ---------------- GEMM2:  g_hs2[m] = dinv[m] * (g_x2[m] @ W2),  N=64, K=128 ----------------
// BM=64, 256 threads, per-thread 4x4 tile.
__global__ __launch_bounds__(256) void gemm2_kernel(const float* __restrict__ W,
                                                    int M) {
    __shared__ __align__(16) float xs[64][128];
    const int row0 = blockIdx.x * 64;
    const int tid = threadIdx.x;

    const float4* x4 = reinterpret_cast<const float4*>(g_x2);
    float4* xs4 = reinterpret_cast<float4*>(&xs[0][0]);
#pragma unroll
    for (int i = 0; i < 8; i++) {
        int idx = i * 256 + tid;
        int r = row0 + (idx >> 5);
        if (r >= M) r = M - 1;
        xs4[idx] = x4[(size_t)r * 32 + (idx & 31)];
    }
    __syncthreads();

    const int cg = tid & 15;      // col group: 4 cols
    const int rg = tid >> 4;      // row group: 4 rows
    const int r0 = rg * 4;
    float acc[4][4] = {};
    const float4* W4 = reinterpret_cast<const float4*>(W);  // row = 16 float4
#pragma unroll 4
    for (int k = 0; k < 128; k++) {
        float4 w = W4[k * 16 + cg];
#pragma unroll
        for (int i = 0; i < 4; i++) {
            float xv = xs[r0 + i][k];
            acc[i][0] += xv * w.x; acc[i][1] += xv * w.y;
            acc[i][2] += xv * w.z; acc[i][3] += xv * w.w;
        }
    }
    float4* out4 = reinterpret_cast<float4*>(g_hs2);
#pragma unroll
    for (int i = 0; i < 4; i++) {
        int row = row0 + r0 + i;
        if (row >= M) break;
        float d = g_dinv[row];
        float4 o;
        o.x = acc[i][0] * d; o.y = acc[i][1] * d;
        o.z = acc[i][2] * d; o.w = acc[i][3] * d;
        out4[(size_t)row * 16 + cg] = o;
    }
}

// ---------------- gather + finalize (layer 1, N=128, relu) ----------------
// One warp per node; each lane owns one float4 column chunk (32 * 4 = 128).
__global__ void gather1_kernel(const float* __restrict__ b) {
    int warp = (blockIdx.x * blockDim.x + threadIdx.x) >> 5;
    int lane = threadIdx.x & 31;
    if (warp >= N_NODES) return;
    const float4* hs4 = reinterpret_cast<const float4*>(g_hs1);

    float4 acc = hs4[(size_t)warp * 32 + lane];  // self-loop term
    int e = g_off[warp], end = g_off[warp + 1];
    for (; e + 4 <= end; e += 4) {
        int s0 = g_esrc[e], s1 = g_esrc[e + 1], s2 = g_esrc[e + 2], s3 = g_esrc[e + 3];
        float4 v0 = hs4[(size_t)s0 * 32 + lane];
        float4 v1 = hs4[(size_t)s1 * 32 + lane];
        float4 v2 = hs4[(size_t)s2 * 32 + lane];
        float4 v3 = hs4[(size_t)s3 * 32 + lane];
        acc.x += v0.x + v1.x + v2.x + v3.x;
        acc.y += v0.y + v1.y + v2.y + v3.y;
        acc.z += v0.z + v1.z + v2.z + v3.z;
        acc.w += v0.w + v1.w + v2.w + v3.w;
    }
    for (; e < end; e++) {
        int s = g_esrc[e];
        float4 v = hs4[(size_t)s * 32 + lane];
        acc.x += v.x; acc.y += v.y; acc.z += v.z; acc.w += v.w;
    }
    float d = g_dinv[warp];
    float4 bv = reinterpret_cast<const float4*>(b)[lane];
    float4 o;
    o.x = fmaxf(fmaf(d, acc.x, bv.x), 0.f);
    o.y = fmaxf(fmaf(d, acc.y, bv.y), 0.f);
    o.z = fmaxf(fmaf(d, acc.z, bv.z), 0.f);
    o.w = fmaxf(fmaf(d, acc.w, bv.w), 0.f);
    reinterpret_cast<float4*>(g_x2)[(size_t)warp * 32 + lane] = o;
}

// ---------------- gather + finalize (layer 2, N=64, no relu) ----------------
// 16 lanes per node (16 * 4 = 64 floats).
__global__ void gather2_kernel(const float* __restrict__ b,
                               float* __restrict__ out) {
    int t = blockIdx.x * blockDim.x + threadIdx.x;
    int node = t >> 4;
    int l = t & 15;
    if (node >= N_NODES) return;
    const float4* hs4 = reinterpret_cast<const float4*>(g_hs2);

    float4 acc = hs4[(size_t)node * 16 + l];  // self-loop term
    int e = g_off[node], end = g_off[node + 1];
    for (; e + 4 <= end; e += 4) {
        int s0 = g_esrc[e], s1 = g_esrc[e + 1], s2 = g_esrc[e + 2], s3 = g_esrc[e + 3];
        float4 v0 = hs4[(size_t)s0 * 16 + l];
        float4 v1 = hs4[(size_t)s1 * 16 + l];
        float4 v2 = hs4[(size_t)s2 * 16 + l];
        float4 v3 = hs4[(size_t)s3 * 16 + l];
        acc.x += v0.x + v1.x + v2.x + v3.x;
        acc.y += v0.y + v1.y + v2.y + v3.y;
        acc.z += v0.z + v1.z + v2.z + v3.z;
        acc.w += v0.w + v1.w + v2.w + v3.w;
    }
    for (; e < end; e++) {
        int s = g_esrc[e];
        float4 v = hs4[(size_t)s * 16 + l];
        acc.x += v.x; acc.y += v.y; acc.z += v.z; acc.w += v.w;
    }
    float d = g_dinv[node];
    float4 bv = reinterpret_cast<const float4*>(b)[l];
    float4 o;
    o.x = fmaf(d, acc.x, bv.x);
    o.y = fmaf(d, acc.y, bv.y);
    o.z = fmaf(d, acc.z, bv.z);
    o.w = fmaf(d, acc.w, bv.w);
    reinterpret_cast<float4*>(out)[(size_t)node * 16 + l] = o;
}

// ---------------- launch (no runtime API calls, no host symbol refs) ----------------

extern "C" void kernel_launch(void* const* d_in, const int* in_sizes, int n_in,
                              void* d_out, int out_size) {
    const float* x   = (const float*)d_in[0];
    const void*  ei  = d_in[1];                 // int32 OR int64 [2, E] — device-detected
    const float* W1  = (const float*)d_in[2];
    const float* b1  = (const float*)d_in[3];
    const float* W2  = (const float*)d_in[4];
    const float* b2  = (const float*)d_in[5];
    float*       out = (float*)d_out;

    const int E = in_sizes[1] / 2;
    const int n = N_NODES;

    // ---- prelude: dtype detect + zero, convert+count, scan, fill ----
    init_kernel<<<cdiv(n, 256), 256>>>((const unsigned int*)ei);
    convert_count_kernel<<<cdiv(E, 256), 256>>>(ei, E);
    scan1_kernel<<<cdiv(n, 1024), 1024>>>(n);
    scan2_kernel<<<1, 64>>>(cdiv(n, 1024));
    scan3_kernel<<<cdiv(n, 256), 256>>>(n, E);
    fill_kernel<<<cdiv(E, 256), 256>>>(E);

    // ---- layer 1 ----
    gemm1_kernel<<<cdiv(n, 64), 256>>>(x, W1, n);
    gather1_kernel<<<cdiv(n * 32, 256), 256>>>(b1);

    // ---- layer 2 ----
    gemm2_kernel<<<cdiv(n, 64), 256>>>(W2, n);
    gather2_kernel<<<cdiv(n * 16, 256), 256>>>(b2, out);
}